// round 13
// baseline (speedup 1.0000x reference)
#include <cuda_runtime.h>

// N-step discounted return, T=1024, B=4096, horizon=16, gamma=0.99.
// g[t,b] = sum_{h=0..15, t+h<T} g^h * r[t+h,b]*m[t+h,b]
//        + g^{min(t+16,T)-t} * V[min(t+15,T-1), b]
//
// R12 structure: 64 cols x 128 output rows per 256-thread block, single wave.
// This round:
//  - grid dims swapped (x = time band, y = column block) so vertically-adjacent
//    CTAs run concurrently -> horizon-overlap rows hit L2, not DRAM
//  - interior bands (t0+WROWS <= T) take a predicate-free staging path

#define TT 1024
#define BB 4096
#define HORIZON 16
#define BCOL 64                     // columns per block
#define TROWS 128                   // output rows per block
#define WROWS 144                   // staged rows (need 143; 144 = even split)
#define CH 32                       // output rows per thread

constexpr float GAMMA = 0.99f;

__host__ __device__ constexpr float gpow(int n) {
    float x = 1.0f;
    for (int i = 0; i < n; ++i) x *= GAMMA;
    return x;
}

__device__ __constant__ float GP[17] = {
    gpow(0),  gpow(1),  gpow(2),  gpow(3),  gpow(4),  gpow(5),
    gpow(6),  gpow(7),  gpow(8),  gpow(9),  gpow(10), gpow(11),
    gpow(12), gpow(13), gpow(14), gpow(15), gpow(16)
};

__global__ __launch_bounds__(256)
void nstep_return_kernel(const float* __restrict__ rew,
                         const float* __restrict__ val,
                         const float* __restrict__ msk,
                         float* __restrict__ out)
{
    __shared__ float rm[WROWS][BCOL];   // 144*64*4 = 36864 B

    const int tid   = threadIdx.x;
    const int t0    = blockIdx.x * TROWS;   // time band (x fast -> bands of one
    const int bcol0 = blockIdx.y * BCOL;    //  column stripe run concurrently)

    constexpr float G16 = gpow(16);

    // ---- Phase 1: stage rm = rew*mask for rows [t0, t0+WROWS) ----
    // 144 rows x 16 float4 = 2304 slots = exactly 9 iterations of 256 threads.
    if (t0 + WROWS <= TT) {
        // Interior band: no bounds checks.
#pragma unroll
        for (int it = 0; it < (WROWS * (BCOL / 4)) / 256; ++it) {
            const int i  = it * 256 + tid;
            const int r  = i >> 4;
            const int c4 = i & 15;
            const unsigned off = (unsigned)((t0 + r) * BB + bcol0 + c4 * 4);
            const float4 rv = *reinterpret_cast<const float4*>(rew + off);
            const float4 mv = *reinterpret_cast<const float4*>(msk + off);
            float4 p = make_float4(rv.x * mv.x, rv.y * mv.y,
                                   rv.z * mv.z, rv.w * mv.w);
            *reinterpret_cast<float4*>(&rm[r][c4 * 4]) = p;
        }
    } else {
        // Last band: zero-fill OOB rows.
#pragma unroll
        for (int it = 0; it < (WROWS * (BCOL / 4)) / 256; ++it) {
            const int i  = it * 256 + tid;
            const int r  = i >> 4;
            const int c4 = i & 15;
            const int tt = t0 + r;

            float4 p = make_float4(0.f, 0.f, 0.f, 0.f);
            if (tt < TT) {
                const unsigned off = (unsigned)(tt * BB + bcol0 + c4 * 4);
                const float4 rv = *reinterpret_cast<const float4*>(rew + off);
                const float4 mv = *reinterpret_cast<const float4*>(msk + off);
                p = make_float4(rv.x * mv.x, rv.y * mv.y,
                                rv.z * mv.z, rv.w * mv.w);
            }
            *reinterpret_cast<float4*>(&rm[r][c4 * 4]) = p;
        }
    }
    __syncthreads();

    // ---- Phase 2: scalar sliding-window recurrence ----
    const int col   = tid & (BCOL - 1);     // 0..63 (warp lanes = consecutive cols)
    const int chunk = tid >> 6;             // 0..3
    const int tl0   = chunk * CH;           // local row base
    const int b     = bcol0 + col;

    // S at local row tl0+CH-1: Horner over rm rows [tl0+CH-1 .. tl0+CH+14].
    float S = 0.0f;
#pragma unroll
    for (int i = CH + 14; i >= CH - 1; --i) {
        S = fmaf(S, GAMMA, rm[tl0 + i][col]);
    }

#pragma unroll
    for (int j = CH - 1; j >= 0; --j) {
        const int t = t0 + tl0 + j;

        float boot;
        if (t + HORIZON <= TT) {
            boot = G16 * val[(unsigned)((t + HORIZON - 1) * BB + b)];
        } else {
            boot = GP[TT - t] * val[(unsigned)((TT - 1) * BB + b)];
        }
        out[(unsigned)(t * BB + b)] = S + boot;

        if (j > 0) {
            // Slide window down: add rm[t-1], drop rm[t+15].
            S = fmaf(GAMMA, S, rm[tl0 + j - 1][col]) - G16 * rm[tl0 + j + 15][col];
        }
    }
}

extern "C" void kernel_launch(void* const* d_in, const int* in_sizes, int n_in,
                              void* d_out, int out_size)
{
    const float* rewards = (const float*)d_in[0];
    const float* values  = (const float*)d_in[1];
    const float* masks   = (const float*)d_in[2];
    float*       out     = (float*)d_out;

    dim3 block(256);
    dim3 grid(TT / TROWS, BB / BCOL);   // (8, 64) = 512 blocks, single wave
    nstep_return_kernel<<<grid, block>>>(rewards, values, masks, out);
}

// round 17
// speedup vs baseline: 1.1910x; 1.1910x over previous
#include <cuda_runtime.h>

// N-step discounted return, T=1024, B=4096, horizon=16, gamma=0.99.
// g[t,b] = sum_{h=0..15, t+h<T} g^h * r[t+h,b]*m[t+h,b]
//        + g^{min(t+16,T)-t} * V[min(t+15,T-1), b]
//
// R12 structure: 64 cols x 128 output rows per 256-thread block, single wave,
// grid (x = column block, y = time band) — consecutive CTAs walk consecutive
// column stripes of the same band (best DRAM locality; R13 showed swapping
// this regresses 20%).
// Added: interior bands (t0+WROWS <= T) use a predicate-free staging path.

#define TT 1024
#define BB 4096
#define HORIZON 16
#define BCOL 64                     // columns per block
#define TROWS 128                   // output rows per block
#define WROWS 144                   // staged rows (need 143; 144 = even split)
#define CH 32                       // output rows per thread

constexpr float GAMMA = 0.99f;

__host__ __device__ constexpr float gpow(int n) {
    float x = 1.0f;
    for (int i = 0; i < n; ++i) x *= GAMMA;
    return x;
}

__device__ __constant__ float GP[17] = {
    gpow(0),  gpow(1),  gpow(2),  gpow(3),  gpow(4),  gpow(5),
    gpow(6),  gpow(7),  gpow(8),  gpow(9),  gpow(10), gpow(11),
    gpow(12), gpow(13), gpow(14), gpow(15), gpow(16)
};

__global__ __launch_bounds__(256)
void nstep_return_kernel(const float* __restrict__ rew,
                         const float* __restrict__ val,
                         const float* __restrict__ msk,
                         float* __restrict__ out)
{
    __shared__ float rm[WROWS][BCOL];   // 144*64*4 = 36864 B

    const int tid   = threadIdx.x;
    const int bcol0 = blockIdx.x * BCOL;    // first column of this block
    const int t0    = blockIdx.y * TROWS;   // first output row of this block

    constexpr float G16 = gpow(16);

    // ---- Phase 1: stage rm = rew*mask for rows [t0, t0+WROWS) ----
    // 144 rows x 16 float4 = 2304 slots = exactly 9 iterations of 256 threads.
    if (t0 + WROWS <= TT) {
        // Interior band: no bounds checks.
#pragma unroll
        for (int it = 0; it < (WROWS * (BCOL / 4)) / 256; ++it) {
            const int i  = it * 256 + tid;
            const int r  = i >> 4;
            const int c4 = i & 15;
            const unsigned off = (unsigned)((t0 + r) * BB + bcol0 + c4 * 4);
            const float4 rv = *reinterpret_cast<const float4*>(rew + off);
            const float4 mv = *reinterpret_cast<const float4*>(msk + off);
            float4 p = make_float4(rv.x * mv.x, rv.y * mv.y,
                                   rv.z * mv.z, rv.w * mv.w);
            *reinterpret_cast<float4*>(&rm[r][c4 * 4]) = p;
        }
    } else {
        // Last band: zero-fill OOB rows.
#pragma unroll
        for (int it = 0; it < (WROWS * (BCOL / 4)) / 256; ++it) {
            const int i  = it * 256 + tid;
            const int r  = i >> 4;
            const int c4 = i & 15;
            const int tt = t0 + r;

            float4 p = make_float4(0.f, 0.f, 0.f, 0.f);
            if (tt < TT) {
                const unsigned off = (unsigned)(tt * BB + bcol0 + c4 * 4);
                const float4 rv = *reinterpret_cast<const float4*>(rew + off);
                const float4 mv = *reinterpret_cast<const float4*>(msk + off);
                p = make_float4(rv.x * mv.x, rv.y * mv.y,
                                rv.z * mv.z, rv.w * mv.w);
            }
            *reinterpret_cast<float4*>(&rm[r][c4 * 4]) = p;
        }
    }
    __syncthreads();

    // ---- Phase 2: scalar sliding-window recurrence ----
    const int col   = tid & (BCOL - 1);     // 0..63 (warp lanes = consecutive cols)
    const int chunk = tid >> 6;             // 0..3
    const int tl0   = chunk * CH;           // local row base
    const int b     = bcol0 + col;

    // S at local row tl0+CH-1: Horner over rm rows [tl0+CH-1 .. tl0+CH+14].
    float S = 0.0f;
#pragma unroll
    for (int i = CH + 14; i >= CH - 1; --i) {
        S = fmaf(S, GAMMA, rm[tl0 + i][col]);
    }

#pragma unroll
    for (int j = CH - 1; j >= 0; --j) {
        const int t = t0 + tl0 + j;

        float boot;
        if (t + HORIZON <= TT) {
            boot = G16 * val[(unsigned)((t + HORIZON - 1) * BB + b)];
        } else {
            boot = GP[TT - t] * val[(unsigned)((TT - 1) * BB + b)];
        }
        out[(unsigned)(t * BB + b)] = S + boot;

        if (j > 0) {
            // Slide window down: add rm[t-1], drop rm[t+15].
            S = fmaf(GAMMA, S, rm[tl0 + j - 1][col]) - G16 * rm[tl0 + j + 15][col];
        }
    }
}

extern "C" void kernel_launch(void* const* d_in, const int* in_sizes, int n_in,
                              void* d_out, int out_size)
{
    const float* rewards = (const float*)d_in[0];
    const float* values  = (const float*)d_in[1];
    const float* masks   = (const float*)d_in[2];
    float*       out     = (float*)d_out;

    dim3 block(256);
    dim3 grid(BB / BCOL, TT / TROWS);   // (64, 8) = 512 blocks, single wave
    nstep_return_kernel<<<grid, block>>>(rewards, values, masks, out);
}